// round 1
// baseline (speedup 1.0000x reference)
#include <cuda_runtime.h>
#include <math.h>

#define Sdim 196
#define Bdim 64
#define Ndim 512
#define Ddim 1024
#define Hdim 8
#define Mc 9                 // 1 + H
#define ROWS (Sdim*Bdim)     // 12544
#define LN_EPS 1e-5f

// ---------------- scratch (static device globals; no allocations) ----------------
__device__ float d_g[Bdim*Ddim];
__device__ float d_common[Bdim*Mc*Ddim];
__device__ float d_Q[Bdim*Hdim*Ddim];
__device__ float d_QW[Bdim*Hdim*Ddim];
__device__ float d_Qd[Bdim*Mc*Ddim];
__device__ float d_Kd[Bdim*Mc*Ddim];
__device__ float d_diff[Bdim*Ddim];
__device__ float d_cvec[Bdim*Ddim];
__device__ float d_hbuf[(size_t)ROWS*Ddim];   // ~51 MB intermediate (pre-LN)

// ---------------- K1: g = mean_s(input), also write common[:,0,:] ----------------
__global__ void mean_kernel(const float* __restrict__ in) {
    int idx = blockIdx.x * blockDim.x + threadIdx.x;   // 0..65535  (= b*D+d)
    float s = 0.f;
    #pragma unroll 4
    for (int t = 0; t < Sdim; t++) s += in[(size_t)t * (Bdim*Ddim) + idx];
    float gv = s * (1.0f / Sdim);
    d_g[idx] = gv;
    int b = idx >> 10, d = idx & 1023;
    d_common[(size_t)b * Mc * Ddim + d] = gv;
}

// ---------------- generic tiled SGEMM: C = A @ op(B) (+bias)(+relu) --------------
// 128x128 tile, Kstep=16, 256 threads, 8x8 per thread (split 4+4 rows/cols).
// BIASMODE: 0 none, 1 bias[col], 2 bias[(row%64)*1024 + col]
template<bool TRANSB, int BIASMODE, bool RELU>
__launch_bounds__(256)
__global__ void sgemm_kernel(const float* __restrict__ A, int lda, size_t strideA,
                             const float* __restrict__ Bm, int ldb, size_t strideB,
                             float* __restrict__ C, int ldc, size_t strideC,
                             const float* __restrict__ bias, size_t strideBias,
                             int M, int N, int K)
{
    A  += (size_t)blockIdx.z * strideA;
    Bm += (size_t)blockIdx.z * strideB;
    C  += (size_t)blockIdx.z * strideC;
    if (BIASMODE != 0) bias += (size_t)blockIdx.z * strideBias;

    __shared__ float As[16][128];
    __shared__ float Bs[16][128];

    int tid = threadIdx.x;
    int tx = tid & 15, ty = tid >> 4;
    int m0 = blockIdx.y * 128, n0 = blockIdx.x * 128;

    float acc[8][8];
    #pragma unroll
    for (int i = 0; i < 8; i++)
        #pragma unroll
        for (int j = 0; j < 8; j++) acc[i][j] = 0.f;

    int lm = tid >> 1;            // 0..127 (A rows / NT B rows)
    int lk = (tid & 1) * 8;       // k sub-offset
    int bkr = tid >> 4;           // 0..15 (NN B rows)
    int bnc = (tid & 15) * 8;     // NN B cols

    for (int k0 = 0; k0 < K; k0 += 16) {
        // --- load A tile (transposed into As[k][m]) ---
        if (m0 + lm < M) {
            const float* ap = A + (size_t)(m0 + lm) * lda + k0 + lk;
            float4 a0 = *(const float4*)ap;
            float4 a1 = *(const float4*)(ap + 4);
            As[lk+0][lm] = a0.x; As[lk+1][lm] = a0.y; As[lk+2][lm] = a0.z; As[lk+3][lm] = a0.w;
            As[lk+4][lm] = a1.x; As[lk+5][lm] = a1.y; As[lk+6][lm] = a1.z; As[lk+7][lm] = a1.w;
        } else {
            #pragma unroll
            for (int i = 0; i < 8; i++) As[lk+i][lm] = 0.f;
        }
        // --- load B tile ---
        if (!TRANSB) {
            const float* bp = Bm + (size_t)(k0 + bkr) * ldb + n0 + bnc;
            *(float4*)&Bs[bkr][bnc]     = *(const float4*)bp;
            *(float4*)&Bs[bkr][bnc + 4] = *(const float4*)(bp + 4);
        } else {
            const float* bp = Bm + (size_t)(n0 + lm) * ldb + k0 + lk;
            float4 b0 = *(const float4*)bp;
            float4 b1 = *(const float4*)(bp + 4);
            Bs[lk+0][lm] = b0.x; Bs[lk+1][lm] = b0.y; Bs[lk+2][lm] = b0.z; Bs[lk+3][lm] = b0.w;
            Bs[lk+4][lm] = b1.x; Bs[lk+5][lm] = b1.y; Bs[lk+6][lm] = b1.z; Bs[lk+7][lm] = b1.w;
        }
        __syncthreads();

        #pragma unroll
        for (int kk = 0; kk < 16; kk++) {
            float4 a0 = *(const float4*)&As[kk][ty*4];
            float4 a1 = *(const float4*)&As[kk][64 + ty*4];
            float4 b0 = *(const float4*)&Bs[kk][tx*4];
            float4 b1 = *(const float4*)&Bs[kk][64 + tx*4];
            float av[8] = {a0.x,a0.y,a0.z,a0.w,a1.x,a1.y,a1.z,a1.w};
            float bv[8] = {b0.x,b0.y,b0.z,b0.w,b1.x,b1.y,b1.z,b1.w};
            #pragma unroll
            for (int i = 0; i < 8; i++)
                #pragma unroll
                for (int j = 0; j < 8; j++)
                    acc[i][j] += av[i] * bv[j];
        }
        __syncthreads();
    }

    #pragma unroll
    for (int i = 0; i < 8; i++) {
        int r = m0 + ((i < 4) ? ty*4 + i : 64 + ty*4 + (i - 4));
        if (r >= M) continue;
        #pragma unroll
        for (int j = 0; j < 8; j++) {
            int c = n0 + ((j < 4) ? tx*4 + j : 64 + tx*4 + (j - 4));
            float v = acc[i][j];
            if (BIASMODE == 1) v += bias[c];
            else if (BIASMODE == 2) v += bias[(size_t)(r & (Bdim - 1)) * Ddim + c];
            if (RELU) v = fmaxf(v, 0.f);
            C[(size_t)r * ldc + c] = v;
        }
    }
}

// ------- K4: per-batch fused aggregated attention (logits+softmax+weighted sum) ---
// One block per b. M[b,h,n] = gnf[b,n,:]·QW[b,h,:]/32 ; softmax over n;
// closest[b,h,:] = sum_n p * gnf[b,n,:]  ->  d_common[b, 1+h, :]
__launch_bounds__(256)
__global__ void agg_attn_kernel(const float* __restrict__ gnf) {
    __shared__ float sQW[Hdim][Ddim];   // 32 KB
    __shared__ float sM[Hdim][Ndim];    // 16 KB
    int b = blockIdx.x;
    int tid = threadIdx.x;
    int warp = tid >> 5, lane = tid & 31;

    const float* qwb = d_QW + (size_t)b * Hdim * Ddim;
    for (int i = tid; i < Hdim*Ddim; i += 256) ((float*)sQW)[i] = qwb[i];
    __syncthreads();

    const float inv_scale = 1.0f / 32.0f;   // 1/sqrt(D)
    for (int n = warp; n < Ndim; n += 8) {
        const float* row = gnf + ((size_t)b * Ndim + n) * Ddim;
        float acc[Hdim];
        #pragma unroll
        for (int h = 0; h < Hdim; h++) acc[h] = 0.f;
        for (int k = lane; k < Ddim; k += 32) {
            float v = row[k];
            #pragma unroll
            for (int h = 0; h < Hdim; h++) acc[h] += v * sQW[h][k];
        }
        #pragma unroll
        for (int h = 0; h < Hdim; h++) {
            float a = acc[h];
            #pragma unroll
            for (int off = 16; off; off >>= 1) a += __shfl_xor_sync(0xffffffffu, a, off);
            if (lane == 0) sM[h][n] = a * inv_scale;
        }
    }
    __syncthreads();

    // softmax: warp h handles head h over 512 logits
    {
        int h = warp;
        float mx = -INFINITY;
        for (int n = lane; n < Ndim; n += 32) mx = fmaxf(mx, sM[h][n]);
        #pragma unroll
        for (int off = 16; off; off >>= 1) mx = fmaxf(mx, __shfl_xor_sync(0xffffffffu, mx, off));
        float sum = 0.f;
        for (int n = lane; n < Ndim; n += 32) {
            float e = expf(sM[h][n] - mx);
            sM[h][n] = e; sum += e;
        }
        #pragma unroll
        for (int off = 16; off; off >>= 1) sum += __shfl_xor_sync(0xffffffffu, sum, off);
        float inv = 1.0f / sum;
        for (int n = lane; n < Ndim; n += 32) sM[h][n] *= inv;
    }
    __syncthreads();

    // weighted sum: thread owns 4 contiguous d values (float4)
    int d0 = tid * 4;
    float acc[Hdim][4];
    #pragma unroll
    for (int h = 0; h < Hdim; h++)
        #pragma unroll
        for (int j = 0; j < 4; j++) acc[h][j] = 0.f;
    for (int n = 0; n < Ndim; n++) {
        float4 v = *(const float4*)(gnf + ((size_t)b * Ndim + n) * Ddim + d0);
        #pragma unroll
        for (int h = 0; h < Hdim; h++) {
            float p = sM[h][n];
            acc[h][0] += p * v.x; acc[h][1] += p * v.y;
            acc[h][2] += p * v.z; acc[h][3] += p * v.w;
        }
    }
    #pragma unroll
    for (int h = 0; h < Hdim; h++) {
        float4 o = make_float4(acc[h][0], acc[h][1], acc[h][2], acc[h][3]);
        *(float4*)(d_common + ((size_t)b * Mc + 1 + h) * Ddim + d0) = o;
    }
}

// ------- K5b: per-batch diff-attention: Md, softmax, column weights, diff ---------
__launch_bounds__(256)
__global__ void diff_attn_kernel() {
    __shared__ float sMd[Mc*Mc];
    __shared__ float sw[Mc];
    int b = blockIdx.x;
    int tid = threadIdx.x;
    int warp = tid >> 5, lane = tid & 31;

    const float* Qb = d_Qd + (size_t)b * Mc * Ddim;
    const float* Kb = d_Kd + (size_t)b * Mc * Ddim;
    for (int p = warp; p < Mc*Mc; p += 8) {
        int m = p / Mc, n = p % Mc;
        float a = 0.f;
        for (int k = lane; k < Ddim; k += 32) a += Qb[m*Ddim + k] * Kb[n*Ddim + k];
        #pragma unroll
        for (int off = 16; off; off >>= 1) a += __shfl_xor_sync(0xffffffffu, a, off);
        if (lane == 0) sMd[p] = a * (1.0f / 32.0f);
    }
    __syncthreads();
    if (tid < Mc) {   // softmax over row tid
        float mx = -INFINITY;
        for (int n = 0; n < Mc; n++) mx = fmaxf(mx, sMd[tid*Mc + n]);
        float s = 0.f;
        for (int n = 0; n < Mc; n++) { float e = expf(sMd[tid*Mc + n] - mx); sMd[tid*Mc + n] = e; s += e; }
        float inv = 1.0f / s;
        for (int n = 0; n < Mc; n++) sMd[tid*Mc + n] *= inv;
    }
    __syncthreads();
    if (tid < Mc) {   // column weight / 9
        float w = 0.f;
        for (int m = 0; m < Mc; m++) w += sMd[m*Mc + tid];
        sw[tid] = w * (1.0f / Mc);
    }
    __syncthreads();
    const float* cb = d_common + (size_t)b * Mc * Ddim;
    for (int d = tid; d < Ddim; d += 256) {
        float ci = 0.f;
        #pragma unroll
        for (int n = 0; n < Mc; n++) ci += sw[n] * cb[n*Ddim + d];
        d_diff[b*Ddim + d] = d_g[b*Ddim + d] - ci;
    }
}

// ---------------- K7: per-row LayerNorm over 1024, write final output ------------
__launch_bounds__(256)
__global__ void ln_kernel(const float* __restrict__ gamma,
                          const float* __restrict__ beta,
                          float* __restrict__ out) {
    __shared__ float red[16];
    int r = blockIdx.x;
    int tid = threadIdx.x, lane = tid & 31, warp = tid >> 5;
    const float* hp = d_hbuf + (size_t)r * Ddim + tid * 4;
    float4 v = *(const float4*)hp;
    float s  = v.x + v.y + v.z + v.w;
    float sq = v.x*v.x + v.y*v.y + v.z*v.z + v.w*v.w;
    #pragma unroll
    for (int off = 16; off; off >>= 1) {
        s  += __shfl_xor_sync(0xffffffffu, s,  off);
        sq += __shfl_xor_sync(0xffffffffu, sq, off);
    }
    if (lane == 0) { red[warp] = s; red[8 + warp] = sq; }
    __syncthreads();
    if (tid == 0) {
        float ts = 0.f, tq = 0.f;
        #pragma unroll
        for (int w = 0; w < 8; w++) { ts += red[w]; tq += red[8 + w]; }
        red[0] = ts; red[8] = tq;
    }
    __syncthreads();
    float mu  = red[0] * (1.0f / Ddim);
    float var = red[8] * (1.0f / Ddim) - mu * mu;
    float rstd = rsqrtf(var + LN_EPS);
    float4 g4 = *(const float4*)(gamma + tid * 4);
    float4 b4 = *(const float4*)(beta  + tid * 4);
    float4 o;
    o.x = (v.x - mu) * rstd * g4.x + b4.x;
    o.y = (v.y - mu) * rstd * g4.y + b4.y;
    o.z = (v.z - mu) * rstd * g4.z + b4.z;
    o.w = (v.w - mu) * rstd * g4.w + b4.w;
    *(float4*)(out + (size_t)r * Ddim + tid * 4) = o;
}

// =================================================================================
extern "C" void kernel_launch(void* const* d_in, const int* in_sizes, int n_in,
                              void* d_out, int out_size) {
    const float* input_feats = (const float*)d_in[0];   // [S,B,D]
    const float* gnf         = (const float*)d_in[1];   // [B,N,D]
    const float* agg_Wq      = (const float*)d_in[2];   // [H,D,D]
    const float* agg_bq      = (const float*)d_in[3];   // [H,D]
    const float* agg_Wk      = (const float*)d_in[4];   // [H,D,D]
    // d_in[5] = agg_bk : constant shift under softmax -> unused
    const float* diff_Wq     = (const float*)d_in[6];   // [D,D]
    const float* diff_bq     = (const float*)d_in[7];   // [D]
    const float* diff_Wk     = (const float*)d_in[8];   // [D,D]
    const float* diff_bk     = (const float*)d_in[9];   // [D]
    const float* upd_W       = (const float*)d_in[10];  // [2D,D]
    const float* upd_b       = (const float*)d_in[11];  // [D]
    const float* ln_gamma    = (const float*)d_in[12];
    const float* ln_beta     = (const float*)d_in[13];
    float* out = (float*)d_out;

    float *p_g, *p_common, *p_Q, *p_QW, *p_Qd, *p_Kd, *p_diff, *p_cvec, *p_h;
    cudaGetSymbolAddress((void**)&p_g,      d_g);
    cudaGetSymbolAddress((void**)&p_common, d_common);
    cudaGetSymbolAddress((void**)&p_Q,      d_Q);
    cudaGetSymbolAddress((void**)&p_QW,     d_QW);
    cudaGetSymbolAddress((void**)&p_Qd,     d_Qd);
    cudaGetSymbolAddress((void**)&p_Kd,     d_Kd);
    cudaGetSymbolAddress((void**)&p_diff,   d_diff);
    cudaGetSymbolAddress((void**)&p_cvec,   d_cvec);
    cudaGetSymbolAddress((void**)&p_h,      d_hbuf);

    // K1: g = mean over S
    mean_kernel<<<(Bdim*Ddim)/256, 256>>>(input_feats);

    // K2: Q[b,h,:] = g @ Wq_h + bq_h   (batched over h)
    sgemm_kernel<false,1,false><<<dim3(Ddim/128, 1, Hdim), 256>>>(
        p_g, Ddim, 0,
        agg_Wq, Ddim, (size_t)Ddim*Ddim,
        p_Q + 0, Hdim*Ddim, (size_t)Ddim,
        agg_bq, (size_t)Ddim,
        Bdim, Ddim, Ddim);

    // K3: QW[b,h,:] = Q[b,h,:] @ Wk_h^T   (batched over h, NT)
    sgemm_kernel<true,0,false><<<dim3(Ddim/128, 1, Hdim), 256>>>(
        p_Q, Hdim*Ddim, (size_t)Ddim,
        agg_Wk, Ddim, (size_t)Ddim*Ddim,
        p_QW, Hdim*Ddim, (size_t)Ddim,
        (const float*)nullptr, 0,
        Bdim, Ddim, Ddim);

    // K4: aggregated attention (logits + softmax + weighted sum) -> common[:,1:9,:]
    agg_attn_kernel<<<Bdim, 256>>>(gnf);

    // K5a: Qd = common @ diff_Wq + bq ; Kd = common @ diff_Wk + bk
    sgemm_kernel<false,1,false><<<dim3(Ddim/128, (Bdim*Mc + 127)/128, 1), 256>>>(
        p_common, Ddim, 0, diff_Wq, Ddim, 0, p_Qd, Ddim, 0,
        diff_bq, 0, Bdim*Mc, Ddim, Ddim);
    sgemm_kernel<false,1,false><<<dim3(Ddim/128, (Bdim*Mc + 127)/128, 1), 256>>>(
        p_common, Ddim, 0, diff_Wk, Ddim, 0, p_Kd, Ddim, 0,
        diff_bk, 0, Bdim*Mc, Ddim, Ddim);

    // K5b: diff = g - common_info
    diff_attn_kernel<<<Bdim, 256>>>();

    // K5c: cvec = diff @ W2 + upd_b   (W2 = upd_W rows D..2D-1)
    sgemm_kernel<false,1,false><<<dim3(Ddim/128, 1, 1), 256>>>(
        p_diff, Ddim, 0,
        upd_W + (size_t)Ddim*Ddim, Ddim, 0,
        p_cvec, Ddim, 0,
        upd_b, 0, Bdim, Ddim, Ddim);

    // K6: hbuf = relu(input_feats @ W1 + cvec[row%64])
    sgemm_kernel<false,2,true><<<dim3(Ddim/128, ROWS/128, 1), 256>>>(
        input_feats, Ddim, 0,
        upd_W, Ddim, 0,
        p_h, Ddim, 0,
        p_cvec, 0,
        ROWS, Ddim, Ddim);

    // K7: layernorm -> out
    ln_kernel<<<ROWS, 256>>>(ln_gamma, ln_beta, out);
}

// round 2
// speedup vs baseline: 2.1482x; 2.1482x over previous
#include <cuda_runtime.h>
#include <math.h>
#include <stdint.h>

#define Sdim 196
#define Bdim 64
#define Ndim 512
#define Ddim 1024
#define Hdim 8
#define Mc 9                 // 1 + H
#define ROWS (Sdim*Bdim)     // 12544
#define LN_EPS 1e-5f

// ---------------- scratch (static device globals; no allocations) ----------------
__device__ float d_g[Bdim*Ddim];
__device__ float d_common[Bdim*Mc*Ddim];
__device__ float d_Q[Bdim*Hdim*Ddim];
__device__ float d_QW[Bdim*Hdim*Ddim];
__device__ float d_M[Bdim*Hdim*Ndim];       // logits -> probs (in place)
__device__ float d_Qd[Bdim*Mc*Ddim];
__device__ float d_Kd[Bdim*Mc*Ddim];
__device__ float d_diff[Bdim*Ddim];
__device__ float d_cvec[Bdim*Ddim];
__device__ float d_hbuf[(size_t)ROWS*Ddim]; // pre-LN activations

// ---------------- tf32 helpers ----------------
__device__ __forceinline__ uint32_t f2tf(float x) {
    uint32_t r; asm("cvt.rna.tf32.f32 %0, %1;" : "=r"(r) : "f"(x)); return r;
}
__device__ __forceinline__ void mma8(float* c, const uint32_t* a, const uint32_t* b) {
    asm volatile("mma.sync.aligned.m16n8k8.row.col.f32.tf32.tf32.f32 "
        "{%0,%1,%2,%3}, {%4,%5,%6,%7}, {%8,%9}, {%0,%1,%2,%3};"
        : "+f"(c[0]), "+f"(c[1]), "+f"(c[2]), "+f"(c[3])
        : "r"(a[0]), "r"(a[1]), "r"(a[2]), "r"(a[3]), "r"(b[0]), "r"(b[1]));
}

// ---------------- K1: g = mean_s(input), also writes common[:,0,:] ----------------
__global__ void mean_kernel(const float* __restrict__ in) {
    int idx = blockIdx.x * blockDim.x + threadIdx.x;   // b*D+d
    float s = 0.f;
    #pragma unroll 4
    for (int t = 0; t < Sdim; t++) s += in[(size_t)t * (Bdim*Ddim) + idx];
    float gv = s * (1.0f / Sdim);
    d_g[idx] = gv;
    int b = idx >> 10, d = idx & 1023;
    d_common[(size_t)b * Mc * Ddim + d] = gv;
}

// ---------------- tf32 tensor-core GEMM ----------------
// C = alpha * A @ op(B) (+bias)(+relu). Row-major A [M,K], row-major C [M,N].
// TRANSB=false: B is [K,N] row-major. TRANSB=true: B is [N,K] row-major (C = A @ B^T).
// BN fixed 128; BM in {64,128}; 256 threads, 8 warps, warp tile (BM==128?64:32) x 32.
// BIASMODE: 0 none, 1 bias[col] (+ z*strideBias), 2 bias[(row&63)*1024 + col]
template<int BM, bool TRANSB, int BIASMODE, bool RELU>
__global__ __launch_bounds__(256) void tf32_gemm(
    const float* __restrict__ A, int lda, size_t strideA,
    const float* __restrict__ Bmat, int ldb, size_t strideB,
    float* __restrict__ C, int ldc, size_t strideC,
    const float* __restrict__ bias, size_t strideBias,
    int M, int K, float alpha)
{
    constexpr int BN = 128, BK = 16, PAD = 8;
    constexpr int WM = (BM == 128) ? 64 : 32;
    constexpr int MI = WM / 16;
    constexpr int NI = 4;  // WN = 32

    __shared__ uint32_t As[BK][BM + PAD];
    __shared__ uint32_t Bs[BK][BN + PAD];

    A    += (size_t)blockIdx.z * strideA;
    Bmat += (size_t)blockIdx.z * strideB;
    C    += (size_t)blockIdx.z * strideC;
    if (BIASMODE == 1) bias += (size_t)blockIdx.z * strideBias;

    const int tid  = threadIdx.x;
    const int warp = tid >> 5, lane = tid & 31;
    const int g = lane >> 2, t = lane & 3;
    const int wm = (warp >> 2) * WM;
    const int wn = (warp & 3) * 32;
    const int m0 = blockIdx.y * BM, n0 = blockIdx.x * BN;

    float acc[MI][NI][4];
    #pragma unroll
    for (int i = 0; i < MI; i++)
        #pragma unroll
        for (int j = 0; j < NI; j++)
            #pragma unroll
            for (int q = 0; q < 4; q++) acc[i][j][q] = 0.f;

    // --- A staging coords: thread covers row am, k-span [ak0, ak0+ACH) ---
    constexpr int ACH = (BK * BM) / 256;            // 8 (BM=128) or 4 (BM=64)
    const int am  = tid % BM;
    const int ak0 = (tid / BM) * ACH;
    const bool avalid = (m0 + am) < M;
    const float* aptr = A + (size_t)(m0 + am) * lda + ak0;

    // --- B staging coords ---
    const int bn  = tid & (BN - 1);                 // TRANSB: n index
    const int bk0 = (tid >> 7) * 8;                 // TRANSB: k-span start
    const int bkr = tid >> 4;                       // NN: k row
    const int bn0 = (tid & 15) * 8;                 // NN: n-span start
    const float* bptrT = Bmat + (size_t)(n0 + bn) * ldb + bk0;
    const float* bptrN = Bmat + (size_t)bkr * ldb + n0 + bn0;

    float ar[ACH];
    float br[8];

    auto loadA = [&](int k0) {
        if (avalid) {
            #pragma unroll
            for (int c = 0; c < ACH; c += 4) {
                float4 v = *(const float4*)(aptr + k0 + c);
                ar[c] = v.x; ar[c+1] = v.y; ar[c+2] = v.z; ar[c+3] = v.w;
            }
        } else {
            #pragma unroll
            for (int c = 0; c < ACH; c++) ar[c] = 0.f;
        }
    };
    auto loadB = [&](int k0) {
        if constexpr (TRANSB) {
            float4 v0 = *(const float4*)(bptrT + k0);
            float4 v1 = *(const float4*)(bptrT + k0 + 4);
            br[0]=v0.x; br[1]=v0.y; br[2]=v0.z; br[3]=v0.w;
            br[4]=v1.x; br[5]=v1.y; br[6]=v1.z; br[7]=v1.w;
        } else {
            const float* p = bptrN + (size_t)k0 * ldb;
            float4 v0 = *(const float4*)p;
            float4 v1 = *(const float4*)(p + 4);
            br[0]=v0.x; br[1]=v0.y; br[2]=v0.z; br[3]=v0.w;
            br[4]=v1.x; br[5]=v1.y; br[6]=v1.z; br[7]=v1.w;
        }
    };
    auto storeAB = [&]() {
        #pragma unroll
        for (int c = 0; c < ACH; c++) As[ak0 + c][am] = f2tf(ar[c]);
        if constexpr (TRANSB) {
            #pragma unroll
            for (int c = 0; c < 8; c++) Bs[bk0 + c][bn] = f2tf(br[c]);
        } else {
            uint4 u0 = make_uint4(f2tf(br[0]), f2tf(br[1]), f2tf(br[2]), f2tf(br[3]));
            uint4 u1 = make_uint4(f2tf(br[4]), f2tf(br[5]), f2tf(br[6]), f2tf(br[7]));
            *(uint4*)&Bs[bkr][bn0]     = u0;
            *(uint4*)&Bs[bkr][bn0 + 4] = u1;
        }
    };

    // prologue
    loadA(0); loadB(0);
    storeAB();
    __syncthreads();

    for (int k0 = BK; ; k0 += BK) {
        const bool more = (k0 < K);
        if (more) { loadA(k0); loadB(k0); }

        #pragma unroll
        for (int kk = 0; kk < BK; kk += 8) {
            uint32_t af[MI][4], bf[NI][2];
            #pragma unroll
            for (int i = 0; i < MI; i++) {
                int mb = wm + i * 16;
                af[i][0] = As[kk + t    ][mb + g];
                af[i][1] = As[kk + t    ][mb + g + 8];
                af[i][2] = As[kk + t + 4][mb + g];
                af[i][3] = As[kk + t + 4][mb + g + 8];
            }
            #pragma unroll
            for (int j = 0; j < NI; j++) {
                int nb = wn + j * 8;
                bf[j][0] = Bs[kk + t    ][nb + g];
                bf[j][1] = Bs[kk + t + 4][nb + g];
            }
            #pragma unroll
            for (int i = 0; i < MI; i++)
                #pragma unroll
                for (int j = 0; j < NI; j++)
                    mma8(acc[i][j], af[i], bf[j]);
        }

        if (!more) break;
        __syncthreads();
        storeAB();
        __syncthreads();
    }

    // epilogue
    #pragma unroll
    for (int i = 0; i < MI; i++) {
        int r0 = m0 + wm + i * 16 + g;
        #pragma unroll
        for (int j = 0; j < NI; j++) {
            int cc = n0 + wn + j * 8 + 2 * t;
            float v0 = acc[i][j][0] * alpha, v1 = acc[i][j][1] * alpha;
            float v2 = acc[i][j][2] * alpha, v3 = acc[i][j][3] * alpha;
            if (BIASMODE == 1) {
                float b0 = bias[cc], b1 = bias[cc + 1];
                v0 += b0; v1 += b1; v2 += b0; v3 += b1;
            } else if (BIASMODE == 2) {
                int rb0 = (r0 & (Bdim - 1)) * Ddim;
                int rb1 = ((r0 + 8) & (Bdim - 1)) * Ddim;
                v0 += bias[rb0 + cc]; v1 += bias[rb0 + cc + 1];
                v2 += bias[rb1 + cc]; v3 += bias[rb1 + cc + 1];
            }
            if (RELU) {
                v0 = fmaxf(v0, 0.f); v1 = fmaxf(v1, 0.f);
                v2 = fmaxf(v2, 0.f); v3 = fmaxf(v3, 0.f);
            }
            if (r0 < M)     *(float2*)(C + (size_t)r0 * ldc + cc)       = make_float2(v0, v1);
            if (r0 + 8 < M) *(float2*)(C + (size_t)(r0 + 8) * ldc + cc) = make_float2(v2, v3);
        }
    }
}

// ---------------- softmax over N=512, one warp per (b,h), in place on d_M --------
__global__ __launch_bounds__(256) void softmax_kernel() {
    int b = blockIdx.x;
    int warp = threadIdx.x >> 5, lane = threadIdx.x & 31;
    float* row = d_M + ((size_t)b * Hdim + warp) * Ndim;
    float mx = -INFINITY;
    for (int n = lane; n < Ndim; n += 32) mx = fmaxf(mx, row[n]);
    #pragma unroll
    for (int off = 16; off; off >>= 1) mx = fmaxf(mx, __shfl_xor_sync(0xffffffffu, mx, off));
    float sum = 0.f;
    float vals[Ndim / 32];
    #pragma unroll
    for (int i = 0; i < Ndim / 32; i++) {
        float e = expf(row[lane + 32 * i] - mx);
        vals[i] = e; sum += e;
    }
    #pragma unroll
    for (int off = 16; off; off >>= 1) sum += __shfl_xor_sync(0xffffffffu, sum, off);
    float inv = 1.0f / sum;
    #pragma unroll
    for (int i = 0; i < Ndim / 32; i++) row[lane + 32 * i] = vals[i] * inv;
}

// ------- diff-attention: Md = Qd·Kd/32, softmax rows, column weights, diff -------
__launch_bounds__(256)
__global__ void diff_attn_kernel() {
    __shared__ float sMd[Mc*Mc];
    __shared__ float sw[Mc];
    int b = blockIdx.x;
    int tid = threadIdx.x;
    int warp = tid >> 5, lane = tid & 31;

    const float* Qb = d_Qd + (size_t)b * Mc * Ddim;
    const float* Kb = d_Kd + (size_t)b * Mc * Ddim;
    for (int p = warp; p < Mc*Mc; p += 8) {
        int m = p / Mc, n = p % Mc;
        float a = 0.f;
        for (int k = lane; k < Ddim; k += 32) a += Qb[m*Ddim + k] * Kb[n*Ddim + k];
        #pragma unroll
        for (int off = 16; off; off >>= 1) a += __shfl_xor_sync(0xffffffffu, a, off);
        if (lane == 0) sMd[p] = a * (1.0f / 32.0f);
    }
    __syncthreads();
    if (tid < Mc) {
        float mx = -INFINITY;
        for (int n = 0; n < Mc; n++) mx = fmaxf(mx, sMd[tid*Mc + n]);
        float s = 0.f;
        for (int n = 0; n < Mc; n++) { float e = expf(sMd[tid*Mc + n] - mx); sMd[tid*Mc + n] = e; s += e; }
        float inv = 1.0f / s;
        for (int n = 0; n < Mc; n++) sMd[tid*Mc + n] *= inv;
    }
    __syncthreads();
    if (tid < Mc) {
        float w = 0.f;
        for (int m = 0; m < Mc; m++) w += sMd[m*Mc + tid];
        sw[tid] = w * (1.0f / Mc);
    }
    __syncthreads();
    const float* cb = d_common + (size_t)b * Mc * Ddim;
    for (int d = tid; d < Ddim; d += 256) {
        float ci = 0.f;
        #pragma unroll
        for (int n = 0; n < Mc; n++) ci += sw[n] * cb[n*Ddim + d];
        d_diff[b*Ddim + d] = d_g[b*Ddim + d] - ci;
    }
}

// ---------------- per-row LayerNorm over 1024, write final output ----------------
__launch_bounds__(256)
__global__ void ln_kernel(const float* __restrict__ gamma,
                          const float* __restrict__ beta,
                          float* __restrict__ out) {
    __shared__ float red[16];
    int r = blockIdx.x;
    int tid = threadIdx.x, lane = tid & 31, warp = tid >> 5;
    const float* hp = d_hbuf + (size_t)r * Ddim + tid * 4;
    float4 v = *(const float4*)hp;
    float s  = v.x + v.y + v.z + v.w;
    float sq = v.x*v.x + v.y*v.y + v.z*v.z + v.w*v.w;
    #pragma unroll
    for (int off = 16; off; off >>= 1) {
        s  += __shfl_xor_sync(0xffffffffu, s,  off);
        sq += __shfl_xor_sync(0xffffffffu, sq, off);
    }
    if (lane == 0) { red[warp] = s; red[8 + warp] = sq; }
    __syncthreads();
    if (tid == 0) {
        float ts = 0.f, tq = 0.f;
        #pragma unroll
        for (int w = 0; w < 8; w++) { ts += red[w]; tq += red[8 + w]; }
        red[0] = ts; red[8] = tq;
    }
    __syncthreads();
    float mu  = red[0] * (1.0f / Ddim);
    float var = red[8] * (1.0f / Ddim) - mu * mu;
    float rstd = rsqrtf(var + LN_EPS);
    float4 g4 = *(const float4*)(gamma + tid * 4);
    float4 b4 = *(const float4*)(beta  + tid * 4);
    float4 o;
    o.x = (v.x - mu) * rstd * g4.x + b4.x;
    o.y = (v.y - mu) * rstd * g4.y + b4.y;
    o.z = (v.z - mu) * rstd * g4.z + b4.z;
    o.w = (v.w - mu) * rstd * g4.w + b4.w;
    *(float4*)(out + (size_t)r * Ddim + tid * 4) = o;
}

// =================================================================================
extern "C" void kernel_launch(void* const* d_in, const int* in_sizes, int n_in,
                              void* d_out, int out_size) {
    const float* input_feats = (const float*)d_in[0];   // [S,B,D]
    const float* gnf         = (const float*)d_in[1];   // [B,N,D]
    const float* agg_Wq      = (const float*)d_in[2];   // [H,D,D]
    const float* agg_bq      = (const float*)d_in[3];   // [H,D]
    const float* agg_Wk      = (const float*)d_in[4];   // [H,D,D]
    // d_in[5] = agg_bk : constant shift under softmax -> unused
    const float* diff_Wq     = (const float*)d_in[6];   // [D,D]
    const float* diff_bq     = (const float*)d_in[7];   // [D]
    const float* diff_Wk     = (const float*)d_in[8];   // [D,D]
    const float* diff_bk     = (const float*)d_in[9];   // [D]
    const float* upd_W       = (const float*)d_in[10];  // [2D,D]
    const float* upd_b       = (const float*)d_in[11];  // [D]
    const float* ln_gamma    = (const float*)d_in[12];
    const float* ln_beta     = (const float*)d_in[13];
    float* out = (float*)d_out;

    float *p_g, *p_common, *p_Q, *p_QW, *p_M, *p_Qd, *p_Kd, *p_diff, *p_cvec, *p_h;
    cudaGetSymbolAddress((void**)&p_g,      d_g);
    cudaGetSymbolAddress((void**)&p_common, d_common);
    cudaGetSymbolAddress((void**)&p_Q,      d_Q);
    cudaGetSymbolAddress((void**)&p_QW,     d_QW);
    cudaGetSymbolAddress((void**)&p_M,      d_M);
    cudaGetSymbolAddress((void**)&p_Qd,     d_Qd);
    cudaGetSymbolAddress((void**)&p_Kd,     d_Kd);
    cudaGetSymbolAddress((void**)&p_diff,   d_diff);
    cudaGetSymbolAddress((void**)&p_cvec,   d_cvec);
    cudaGetSymbolAddress((void**)&p_h,      d_hbuf);

    // K1: g = mean over S (also common[:,0,:])
    mean_kernel<<<(Bdim*Ddim)/256, 256>>>(input_feats);

    // K2: Q[b,(h,e)] = g @ Wq_h + bq_h  (batched over h)   M=64,N=1024,K=1024
    tf32_gemm<64,false,1,false><<<dim3(8,1,Hdim), 256>>>(
        p_g, Ddim, 0,
        agg_Wq, Ddim, (size_t)Ddim*Ddim,
        p_Q, Hdim*Ddim, (size_t)Ddim,
        agg_bq, (size_t)Ddim,
        Bdim, Ddim, 1.0f);

    // K3: QW[b,h,d] = Q[b,h,:] @ Wk_h^T   (TRANSB, batched over h)
    tf32_gemm<64,true,0,false><<<dim3(8,1,Hdim), 256>>>(
        p_Q, Hdim*Ddim, (size_t)Ddim,
        agg_Wk, Ddim, (size_t)Ddim*Ddim,
        p_QW, Hdim*Ddim, (size_t)Ddim,
        (const float*)nullptr, 0,
        Bdim, Ddim, 1.0f);

    // K4a: logits M[b,h,n] = (QW[b] @ gnf[b]^T)/32   M=8,N=512,K=1024, batch=B
    tf32_gemm<64,true,0,false><<<dim3(4,1,Bdim), 256>>>(
        p_QW, Ddim, (size_t)Hdim*Ddim,
        gnf, Ddim, (size_t)Ndim*Ddim,
        p_M, Ndim, (size_t)Hdim*Ndim,
        (const float*)nullptr, 0,
        Hdim, Ddim, 1.0f/32.0f);

    // K4b: softmax over n (in place)
    softmax_kernel<<<Bdim, 256>>>();

    // K4c: closest = P @ gnf -> common[:,1:9,:]   M=8,N=1024,K=512, batch=B
    tf32_gemm<64,false,0,false><<<dim3(8,1,Bdim), 256>>>(
        p_M, Ndim, (size_t)Hdim*Ndim,
        gnf, Ddim, (size_t)Ndim*Ddim,
        p_common + Ddim, Ddim, (size_t)Mc*Ddim,
        (const float*)nullptr, 0,
        Hdim, Ndim, 1.0f);

    // K5a: Qd = common @ diff_Wq + bq ; Kd = common @ diff_Wk + bk  (M=576)
    tf32_gemm<64,false,1,false><<<dim3(8,Bdim*Mc/64,1), 256>>>(
        p_common, Ddim, 0, diff_Wq, Ddim, 0, p_Qd, Ddim, 0,
        diff_bq, 0, Bdim*Mc, Ddim, 1.0f);
    tf32_gemm<64,false,1,false><<<dim3(8,Bdim*Mc/64,1), 256>>>(
        p_common, Ddim, 0, diff_Wk, Ddim, 0, p_Kd, Ddim, 0,
        diff_bk, 0, Bdim*Mc, Ddim, 1.0f);

    // K5b: diff = g - common_info
    diff_attn_kernel<<<Bdim, 256>>>();

    // K5c: cvec = diff @ W2 + upd_b   (W2 = upd_W rows D..2D-1)
    tf32_gemm<64,false,1,false><<<dim3(8,1,1), 256>>>(
        p_diff, Ddim, 0,
        upd_W + (size_t)Ddim*Ddim, Ddim, 0,
        p_cvec, Ddim, 0,
        upd_b, 0, Bdim, Ddim, 1.0f);

    // K6: hbuf = relu(input_feats @ W1 + cvec[row%64])   M=12544,N=1024,K=1024
    tf32_gemm<128,false,2,true><<<dim3(8,ROWS/128,1), 256>>>(
        input_feats, Ddim, 0,
        upd_W, Ddim, 0,
        p_h, Ddim, 0,
        p_cvec, 0, ROWS, Ddim, 1.0f);

    // K7: layernorm -> out
    ln_kernel<<<ROWS, 256>>>(ln_gamma, ln_beta, out);
}